// round 14
// baseline (speedup 1.0000x reference)
#include <cuda_runtime.h>
#include <cuda_fp16.h>

// APPNP: h_{k+1} = (1-a) * Dinv(A+I)Dinv * h_k + a * x,  K=5, a=0.8
// g = dinv .* h stored FP16, rows padded to 128B. Dim-parallel: lane<24 owns
// one half2 chunk. Lanes 24..31 (otherwise idle) prefetch a 32-edge batch of
// CSR indices in parallel; inner loop gets each quad's indices via shfl
// (26 cyc) instead of a chained L2 load (~250+ cyc). HADD2 quad tree.

#define NN 100000
#define EE 1600000
#define F2 24               // chunks per row (48 dims / 2)
#define GS 32               // half2 stride per fp16 row (128B padded)
#define CSR_CAP (EE + 3 * NN + 4)
#define ALPHA 0.8f

// ---------------- device scratch (static, no allocation) ----------------
__device__ int     g_ecount[NN];    // zero at every kernel_launch entry (invariant)
__device__ int     g_total;         // zero at entry (invariant)
__device__ float   g_dinv[NN];
__device__ int     g_colstart[NN];
__device__ int     g_colend[NN];    // padded end (multiple-of-4 segment)
__device__ int     g_rank[EE];
__device__ int4    g_csr4[CSR_CAP / 4 + 1];
__device__ __half2 g_bufA[(NN + 1) * GS];   // row NN = permanent zeros
__device__ __half2 g_bufB[(NN + 1) * GS];   // (never written)

// ---------------- preprocessing ----------------
__global__ void k_hist(const int* __restrict__ col) {
    int e = blockIdx.x * blockDim.x + threadIdx.x;
    if (e < EE) g_rank[e] = atomicAdd(&g_ecount[col[e]], 1);
}

__global__ void k_alloc() {
    int v = blockIdx.x * blockDim.x + threadIdx.x;
    if (v < NN) {
        int c  = g_ecount[v];
        int cp = (c + 3) & ~3;
        int p  = atomicAdd(&g_total, cp);       // g_total starts 0 -> p 4-aligned
        g_colstart[v] = p;
        g_colend[v]   = p + cp;
        int* csr = (int*)g_csr4;
        for (int j = c; j < cp; j++) csr[p + j] = NN;   // zero-row padding
        g_dinv[v] = rsqrtf((float)(c + 1));     // +1 self loop
    }
}

// scatter (atomic-free) + g0 = fp16(dinv.*x) + restore zero-invariant
__global__ void k_scatter_fused(const int* __restrict__ row, const int* __restrict__ col,
                                const float2* __restrict__ x2, __half2* __restrict__ g0) {
    int t = blockIdx.x * blockDim.x + threadIdx.x;
    if (t < EE) {
        int p = g_colstart[col[t]] + g_rank[t];
        ((int*)g_csr4)[p] = row[t];
    }
    if (t < NN * F2) {
        int v = t / F2, c = t % F2;
        float s = g_dinv[v];
        float2 a = x2[t];
        g0[v * GS + c] = __floats2half2_rn(a.x * s, a.y * s);
    }
    if (t < NN) g_ecount[t] = 0;       // ecount dead after k_alloc; re-zero
    if (t == 0) g_total = 0;
}

// ---------------- propagation ----------------
// Warp per node; lane<24 owns chunk `lane`; lanes 24..31 prefetch indices.
template <bool WRITE_H>
__global__ void __launch_bounds__(256, 7) k_propagate(const __half2* __restrict__ gin,
                                                      const float2* __restrict__ x2,
                                                      void* __restrict__ gout_) {
    int v    = (blockIdx.x * blockDim.x + threadIdx.x) >> 5;
    int lane = threadIdx.x & 31;
    if (v >= NN) return;

    int b   = g_colstart[v];
    int end = g_colend[v];                 // multiple-of-4 segment, no tail
    bool act = (lane < F2);

    float2 acc = make_float2(0.f, 0.f);

    while (b < end) {
        int batch_end = min(b + 32, end);

        // lanes 24..31: parallel-load up to 8 int4 (32 edge indices)
        int4 myidx = make_int4(NN, NN, NN, NN);
        if (lane >= 24) {
            int pos = b + ((lane - 24) << 2);
            if (pos < batch_end) myidx = __ldg(&g_csr4[pos >> 2]);
        }

        int q = 24;
        for (; b < batch_end; b += 4, q++) {
            int rx = __shfl_sync(0xffffffffu, myidx.x, q);
            int ry = __shfl_sync(0xffffffffu, myidx.y, q);
            int rz = __shfl_sync(0xffffffffu, myidx.z, q);
            int rw = __shfl_sync(0xffffffffu, myidx.w, q);
            if (act) {
                __half2 u0 = __ldg(&gin[rx * GS + lane]);
                __half2 u1 = __ldg(&gin[ry * GS + lane]);
                __half2 u2 = __ldg(&gin[rz * GS + lane]);
                __half2 u3 = __ldg(&gin[rw * GS + lane]);
                __half2 s  = __hadd2(__hadd2(u0, u1), __hadd2(u2, u3));
                float2  f  = __half22float2(s);
                acc.x += f.x;
                acc.y += f.y;
            }
        }
    }

    if (act) {
        float di  = g_dinv[v];
        float2 gv = __half22float2(__ldg(&gin[v * GS + lane]));   // self loop
        float2 xx = __ldg(&x2[v * F2 + lane]);

        float2 h;
        h.x = (1.0f - ALPHA) * (di * (acc.x + gv.x)) + ALPHA * xx.x;
        h.y = (1.0f - ALPHA) * (di * (acc.y + gv.y)) + ALPHA * xx.y;

        if (WRITE_H) {
            ((float2*)gout_)[v * F2 + lane] = h;
        } else {   // store g = dinv*h as fp16 for next step
            ((__half2*)gout_)[v * GS + lane] = __floats2half2_rn(h.x * di, h.y * di);
        }
    }
}

// ---------------- launch ----------------
extern "C" void kernel_launch(void* const* d_in, const int* in_sizes, int n_in,
                              void* d_out, int out_size) {
    const float2* x2 = (const float2*)d_in[0];
    const int*    ei = (const int*)d_in[1];
    const int* row = ei;          // edge_index[0]
    const int* col = ei + EE;     // edge_index[1]

    __half2 *pA, *pB;
    cudaGetSymbolAddress((void**)&pA, g_bufA);
    cudaGetSymbolAddress((void**)&pB, g_bufB);

    k_hist<<<(EE + 255) / 256, 256>>>(col);                        // launch 1
    k_alloc<<<(NN + 255) / 256, 256>>>();                          // launch 2
    const int FT = NN * F2;
    k_scatter_fused<<<(FT + 255) / 256, 256>>>(row, col, x2, pA);  // launch 3

    const int PBLK = 256;                       // 8 warps = 8 nodes per block
    const int PGRID = (NN + 7) / 8;             // 12500
    k_propagate<false><<<PGRID, PBLK>>>(pA, x2, pB);    // launch 4 <- profiled
    k_propagate<false><<<PGRID, PBLK>>>(pB, x2, pA);
    k_propagate<false><<<PGRID, PBLK>>>(pA, x2, pB);
    k_propagate<false><<<PGRID, PBLK>>>(pB, x2, pA);
    k_propagate<true ><<<PGRID, PBLK>>>(pA, x2, d_out); // step 5 -> h (fp32)
}